// round 15
// baseline (speedup 1.0000x reference)
#include <cuda_runtime.h>
#include <cuda_bf16.h>
#include <math.h>
#include <float.h>
#include <stdint.h>

#define N_B   32
#define N_F   80
#define KLEN  251
#define T_IN  32000
#define T_OUT (T_IN - KLEN + 1)   /* 31750 */
#define T_TILE 1024               /* per CTA: 8 subtiles of 128 t */
#define NT     32                 /* tiles per batch row */
#define XLEN   1280               /* staged x elems: covers window 8 */

/* ---- arch feature gate: tcgen05 only exists in the sm_10xa pass ---- */
#if defined(__CUDA_ARCH__) && (defined(__CUDA_ARCH_FEAT_SM103_ALL) || \
    defined(__CUDA_ARCH_FEAT_SM100_ALL) || defined(__CUDA_ARCH_FEAT_SM101_ALL))
#define HAS_TC 1
#else
#define HAS_TC 0
#endif

/* ---- dynamic smem layout (bytes) ---- */
#define OFF_TMEM  0
#define OFF_MBARA 16
#define OFF_MBARB 24
#define OFF_XH    1024            /* 1280 bf16 = 2560B */
#define OFF_XL    3584            /* ends 6144 */
#define OFF_A     8192            /* [hi s0][hi s1][lo s0][lo s1] x 32768B */
#define OFF_FHH   139264          /* 80x256 bf16 blocked SW128 = 40960B */
#define OFF_FHL   180224          /* 40960B, ends 221184 */
#define SMEM_TOTAL 221184

/* TMEM: double-buffered D, 128-col aligned bases; alloc 256 cols */
#define TM_D0 0
#define TM_D1 128

/* ---- device globals (no allocs allowed) ---- */
__device__ float         g_filt[N_F * KLEN];     /* fp32, fallback only */
__device__ unsigned char g_hhb[40960];           /* blocked+swizzled bf16 hi */
__device__ unsigned char g_hlb[40960];           /* blocked+swizzled bf16 lo */

/* filter (f,k) -> byte offset, blocked SW128: atom = 8f x 64k (1024B),
   10 f-atoms, 4 k-atoms, atom_off = (f>>3) + (k>>6)*10 */
__host__ __device__ __forceinline__ uint32_t filt_boff(int f, int k) {
    uint32_t o = ((uint32_t)(f >> 3) + (uint32_t)(k >> 6) * 10u) * 1024u
               + (uint32_t)(f & 7) * 128u + (uint32_t)(k & 63) * 2u;
    return o ^ ((o >> 3) & 0x70);
}

/* ---------------- kernel 1: build filters (validated math) ----------------- */
__global__ void build_filters_k(const float* __restrict__ b1,
                                const float* __restrict__ band)
{
    const int f = blockIdx.x;
    const int i = threadIdx.x;
    __shared__ float red[256];

    const float min_f = 50.0f / 16000.0f;
    const float beg   = fabsf(b1[f])   + min_f;
    const float endf  = beg + fabsf(band[f]) + min_f;
    const float twopi = 6.283185307179586f;

    float bp = 0.0f;
    float v  = -FLT_MAX;
    if (i < KLEN) {
        const int d = i - 125;
        float sb, se;
        if (d == 0) { sb = 1.0f; se = 1.0f; }
        else {
            const float tr = fabsf((float)d) * (1.0f / 16000.0f);
            const float ab = twopi * (beg  * 16000.0f) * tr;
            const float ae = twopi * (endf * 16000.0f) * tr;
            sb = sinf(ab) / ab;
            se = sinf(ae) / ae;
        }
        bp = 2.0f * endf * se - 2.0f * beg * sb;
        v  = bp;
    }
    red[i] = v;
    __syncthreads();
    #pragma unroll
    for (int s = 128; s > 0; s >>= 1) {
        if (i < s) red[i] = fmaxf(red[i], red[i + s]);
        __syncthreads();
    }
    const float mx = red[0];

    float val = 0.0f;
    if (i < KLEN) {
        const float n = (251.0f * (float)i) / 250.0f;
        const float w = 0.54f - 0.46f * cosf(twopi * n / 251.0f);
        val = (bp / mx) * w;
        g_filt[f * KLEN + i] = val;
    }
    if (i < 256) {  /* all 256 padded taps (val=0 beyond KLEN) */
        const __nv_bfloat16 h = __float2bfloat16(val);
        const __nv_bfloat16 l = __float2bfloat16(val - __bfloat162float(h));
        const uint32_t bo = filt_boff(f, i);
        *(__nv_bfloat16*)(g_hhb + bo) = h;
        *(__nv_bfloat16*)(g_hlb + bo) = l;
    }
}

#if HAS_TC
/* ---------------- PTX helpers (sm_103a pass only) -------------------------- */
__device__ __forceinline__ uint32_t elect_one_pred() {
    uint32_t p;
    asm volatile("{\n\t.reg .pred p;\n\telect.sync _|p, 0xFFFFFFFF;\n\t"
                 "selp.b32 %0, 1, 0, p;\n\t}" : "=r"(p));
    return p;
}
__device__ __forceinline__ uint32_t smem_to_u32(const void* p) {
    uint32_t a;
    asm("{ .reg .u64 t; cvta.to.shared.u64 t, %1; cvt.u32.u64 %0, t; }" : "=r"(a) : "l"(p));
    return a;
}
#define MBARRIER_INIT(addr, cnt) \
    asm volatile("mbarrier.init.shared.b64 [%0], %1;" :: "r"((uint32_t)(addr)), "r"((uint32_t)(cnt)) : "memory")
#define MBARRIER_WAIT_PARITY(mbar_a, par) do { \
    uint32_t _m = (uint32_t)(mbar_a), _p = (uint32_t)(par), _d; \
    asm volatile("{\n\t.reg .pred p;\n\t" \
        "mbarrier.try_wait.parity.acquire.cta.shared::cta.b64 p, [%1], %2;\n\t" \
        "selp.b32 %0, 1, 0, p;\n\t}" : "=r"(_d) : "r"(_m), "r"(_p) : "memory"); \
    if (!_d) { \
        asm volatile("{\n\t.reg .pred P1;\n\t" \
            "WL_%=:\n\t" \
            "mbarrier.try_wait.parity.acquire.cta.shared::cta.b64 P1, [%0], %1, 0x989680;\n\t" \
            "@P1 bra.uni WD_%=;\n\t" \
            "bra.uni WL_%=;\n\t" \
            "WD_%=:\n\t}" :: "r"(_m), "r"(_p) : "memory"); \
    } \
} while (0)
#define TCGEN05_ALLOC(res, n) \
    asm volatile("tcgen05.alloc.cta_group::1.sync.aligned.shared::cta.b32 [%0], %1;" \
        :: "r"((uint32_t)(res)), "r"((uint32_t)(n)) : "memory")
#define TCGEN05_DEALLOC(t, n) \
    asm volatile("tcgen05.dealloc.cta_group::1.sync.aligned.b32 %0, %1;" :: "r"(t), "r"((uint32_t)(n)))
#define TCGEN05_WAIT_LD() asm volatile("tcgen05.wait::ld.sync.aligned;" ::: "memory")
#define TCGEN05_FENCE_BEFORE() asm volatile("tcgen05.fence::before_thread_sync;" ::: "memory")
#define TCGEN05_FENCE_AFTER()  asm volatile("tcgen05.fence::after_thread_sync;" ::: "memory")
#define TCGEN05_COMMIT(mbar) \
    asm volatile("tcgen05.commit.cta_group::1.mbarrier::arrive::one.shared::cluster.b64 [%0];" \
        :: "r"((uint32_t)(mbar)) : "memory")

/* SS-mode f16 MMA (validated form, cg1) */
__device__ __forceinline__ void mma_f16_ss(uint32_t d, uint64_t ad, uint64_t bd,
                                           uint32_t idesc, uint32_t en) {
    uint32_t z = 0;
    asm volatile("{\n\t.reg .pred p;\n\tsetp.ne.u32 p, %5, 0;\n\t"
        "tcgen05.mma.cta_group::1.kind::f16 [%0], %1, %2, %3, {%4, %4, %4, %4}, p;\n\t}"
        :: "r"(d), "l"(ad), "l"(bd), "r"(idesc), "r"(z), "r"(en) : "memory");
}
#define TCGEN05_LD_32X32B_X32(r, tmem_addr) \
    asm volatile("tcgen05.ld.sync.aligned.32x32b.x32.b32 " \
        "{%0, %1, %2, %3, %4, %5, %6, %7, %8, %9, %10, %11, %12, %13, %14, %15, " \
        " %16, %17, %18, %19, %20, %21, %22, %23, %24, %25, %26, %27, %28, %29, %30, %31}, [%32];" \
        : "=r"((r)[0]),  "=r"((r)[1]),  "=r"((r)[2]),  "=r"((r)[3]), \
          "=r"((r)[4]),  "=r"((r)[5]),  "=r"((r)[6]),  "=r"((r)[7]), \
          "=r"((r)[8]),  "=r"((r)[9]),  "=r"((r)[10]), "=r"((r)[11]), \
          "=r"((r)[12]), "=r"((r)[13]), "=r"((r)[14]), "=r"((r)[15]), \
          "=r"((r)[16]), "=r"((r)[17]), "=r"((r)[18]), "=r"((r)[19]), \
          "=r"((r)[20]), "=r"((r)[21]), "=r"((r)[22]), "=r"((r)[23]), \
          "=r"((r)[24]), "=r"((r)[25]), "=r"((r)[26]), "=r"((r)[27]), \
          "=r"((r)[28]), "=r"((r)[29]), "=r"((r)[30]), "=r"((r)[31]) \
        : "r"(tmem_addr))
#define TCGEN05_LD_32X32B_X16(r, tmem_addr) \
    asm volatile("tcgen05.ld.sync.aligned.32x32b.x16.b32 " \
        "{%0, %1, %2, %3, %4, %5, %6, %7, %8, %9, %10, %11, %12, %13, %14, %15}, [%16];" \
        : "=r"((r)[0]),  "=r"((r)[1]),  "=r"((r)[2]),  "=r"((r)[3]), \
          "=r"((r)[4]),  "=r"((r)[5]),  "=r"((r)[6]),  "=r"((r)[7]), \
          "=r"((r)[8]),  "=r"((r)[9]),  "=r"((r)[10]), "=r"((r)[11]), \
          "=r"((r)[12]), "=r"((r)[13]), "=r"((r)[14]), "=r"((r)[15]) \
        : "r"(tmem_addr))

/* SW128 K-major descriptor base (validated constants) */
static constexpr uint64_t SMEM_DESC_BASE_SW128 =
    (uint64_t(2)  << 61) | (uint64_t(1) << 46) | (uint64_t(64) << 32) | (uint64_t(1) << 16);
#define MAKE_SMEM_DESC(base_addr) \
    (SMEM_DESC_BASE_SW128 | ((uint64_t)((base_addr) >> 4) & 0x3FFF))

/* idesc kind::f16: M=128, N=64 / N=16 */
static constexpr uint32_t IDESC_N64 =
    (1u << 4) | (1u << 7) | (1u << 10) | (8u << 17) | (8u << 24);
static constexpr uint32_t IDESC_N16 =
    (1u << 4) | (1u << 7) | (1u << 10) | (2u << 17) | (8u << 24);

/* ---- build one 128x128 window (this wg's split) into a slot.
   Window w: row m holds x[t0 + 128*w + m + k'], k' = 0..127.
   Blocked SW128: atom = 8m x 64k; 16 m-atoms, 2 k-atoms (stride 16 atoms). ---- */
__device__ __forceinline__ void build_window(char* Abuf, const uint32_t* xw,
                                             int w, int m, uint32_t selp)
{
    const uint32_t w0i = (uint32_t)(128 * w + m) >> 1;
    uint32_t prev = xw[w0i];
    #pragma unroll 1
    for (int cj = 0; cj < 16; cj++) {       /* 16B chunk = 8 bf16 */
        uint32_t q0, q1, q2, q3, nx;
        nx = xw[w0i + 4*cj + 1]; q0 = __byte_perm(prev, nx, selp); prev = nx;
        nx = xw[w0i + 4*cj + 2]; q1 = __byte_perm(prev, nx, selp); prev = nx;
        nx = xw[w0i + 4*cj + 3]; q2 = __byte_perm(prev, nx, selp); prev = nx;
        nx = xw[w0i + 4*cj + 4]; q3 = __byte_perm(prev, nx, selp); prev = nx;
        uint32_t o = ((uint32_t)(m >> 3) + (uint32_t)(cj >> 3) * 16u) * 1024u
                   + (uint32_t)(m & 7) * 128u + (uint32_t)(cj & 7) * 16u;
        o ^= (o >> 3) & 0x70;
        *(uint4*)(Abuf + o) = make_uint4(q0, q1, q2, q3);
    }
}

/* ---- issue one MMA half: window slot, filter ksteps hk*8..hk*8+7 ---- */
__device__ __forceinline__ void issue_half(uint32_t sb, uint32_t d,
                                           uint32_t slot, int hk, int fresh)
{
    #pragma unroll 1
    for (int s = 0; s < 3; s++) {
        const uint32_t aoff = OFF_A + ((s == 1) ? 65536u : 0u) + slot * 32768u;
        const uint64_t ad0 = MAKE_SMEM_DESC(sb + aoff);
        const uint32_t fof = (s == 2) ? OFF_FHL : OFF_FHH;
        const uint64_t bd0 = MAKE_SMEM_DESC(sb + fof);          /* f0..63  */
        const uint64_t bd1 = MAKE_SMEM_DESC(sb + fof + 8192);   /* f64..79 */
        #pragma unroll
        for (int ks = 0; ks < 8; ks++) {
            const uint64_t ao = 1024u * (ks >> 2) + 2u * (ks & 3);
            const int gk = 8 * hk + ks;
            const uint64_t bo = 640u * (gk >> 2) + 2u * (gk & 3);
            const uint32_t en = (fresh && s == 0 && ks == 0) ? 0u : 1u;
            mma_f16_ss(d,      ad0 + ao, bd0 + bo, IDESC_N64, en);
            mma_f16_ss(d + 64, ad0 + ao, bd1 + bo, IDESC_N16, en);
        }
    }
}

/* ---- drain one D buffer, split across warpgroups.
   LDTM warp-collective: always executed; per-lane stores guarded. ---- */
__device__ __forceinline__ void drain_d(uint32_t db, float* __restrict__ outb,
                                        int t, int wg)
{
    if (wg == 0) {     /* cols 0..31 and 64..79 */
        uint32_t r0[32], r2[16];
        TCGEN05_LD_32X32B_X32(r0, db);
        TCGEN05_LD_32X32B_X16(r2, db + 64);
        TCGEN05_WAIT_LD();
        if (t < T_OUT) {
            float* op = outb + t;
            #pragma unroll
            for (int c = 0; c < 32; c++) op[(size_t)c * T_OUT] = __uint_as_float(r0[c]);
            #pragma unroll
            for (int c = 0; c < 16; c++) op[(size_t)(64 + c) * T_OUT] = __uint_as_float(r2[c]);
        }
    } else {           /* cols 32..63 */
        uint32_t r1[32];
        TCGEN05_LD_32X32B_X32(r1, db + 32);
        TCGEN05_WAIT_LD();
        if (t < T_OUT) {
            float* op = outb + t;
            #pragma unroll
            for (int c = 0; c < 32; c++) op[(size_t)(32 + c) * T_OUT] = __uint_as_float(r1[c]);
        }
    }
}
#endif /* HAS_TC */

/* ---------------- main kernel: tensor path OR fp32 fallback --------------- */
__global__ void __launch_bounds__(256, 1)
#if HAS_TC
__cluster_dims__(1, 1, 1)
#endif
sinc_mma_k(const float* __restrict__ x, float* __restrict__ out)
{
    extern __shared__ char smem[];
    const int tid = threadIdx.x;
    const int b   = blockIdx.y;
    const int t0  = blockIdx.x * T_TILE;

#if HAS_TC
    const uint32_t sb = smem_to_u32(smem);
    const int wid  = tid >> 5;
    const int lane = tid & 31;
    const int wg   = tid >> 7;          /* warpgroup: 0 -> hi split, 1 -> lo */
    const int m    = tid & 127;         /* A row 0..127 */

    if (wid == 0) TCGEN05_ALLOC(sb + OFF_TMEM, 256);
    if (tid == 0) { MBARRIER_INIT(sb + OFF_MBARA, 1); MBARRIER_INIT(sb + OFF_MBARB, 1); }

    /* stage x (bf16 hi/lo split) */
    {
        const float* xb = x + (size_t)b * T_IN;
        __nv_bfloat16* xh = (__nv_bfloat16*)(smem + OFF_XH);
        __nv_bfloat16* xl = (__nv_bfloat16*)(smem + OFF_XL);
        for (int i = tid; i < XLEN; i += 256) {
            const int g = t0 + i;
            const float v = (g < T_IN) ? xb[g] : 0.0f;
            const __nv_bfloat16 h = __float2bfloat16(v);
            xh[i] = h;
            xl[i] = __float2bfloat16(v - __bfloat162float(h));
        }
    }
    /* stage filters (raw copy preserves blocked+swizzled layout) */
    {
        const uint4* shh = (const uint4*)g_hhb;
        const uint4* shl = (const uint4*)g_hlb;
        uint4* dhh = (uint4*)(smem + OFF_FHH);
        uint4* dhl = (uint4*)(smem + OFF_FHL);
        for (int j = tid; j < 2560; j += 256) { dhh[j] = shh[j]; dhl[j] = shl[j]; }
    }
    __syncthreads();

    uint32_t tmem;
    asm volatile("ld.shared.b32 %0, [%1];" : "=r"(tmem) : "r"(sb + OFF_TMEM));

    const uint32_t selp = (m & 1) ? 0x5432u : 0x3210u;
    const uint32_t* xw = (const uint32_t*)(smem + (wg ? OFF_XL : OFF_XH));
    char* Abase = smem + OFF_A + (wg ? 65536 : 0);   /* this wg's 2 slots */
    float* outb = out + (size_t)b * N_F * T_OUT;

    /* prologue: window 0 into slot 0 */
    build_window(Abase, xw, 0, m, selp);
    asm volatile("fence.proxy.async.shared::cta;" ::: "memory");
    __syncthreads();

    #pragma unroll 1
    for (int i = 0; i < 8; i++) {
        const uint32_t d = tmem + ((i & 1) ? TM_D1 : TM_D0);

        /* wait half1(i-1) done (mbarA): frees slot (i+1)&1 for window i+1.
           ABA-safe: half1(i) commit not yet issued -> completions in {i-1,i}. */
        if (i > 0) { MBARRIER_WAIT_PARITY(sb + OFF_MBARA, (i - 1) & 1); TCGEN05_FENCE_AFTER(); }

        /* issue half1(i): window i (slot i&1), ksteps 0..7, fresh accum */
        if (wid == 0 && elect_one_pred()) {
            issue_half(sb, d, (uint32_t)i & 1u, 0, 1);
            TCGEN05_COMMIT(sb + OFF_MBARA);
        }

        /* wait half2(i-1) done (mbarB): frees D[(i-1)&1] for drain.
           ABA-safe: half2(i) commit not yet issued. */
        if (i > 0) { MBARRIER_WAIT_PARITY(sb + OFF_MBARB, (i - 1) & 1); TCGEN05_FENCE_AFTER(); }

        /* build window i+1 + drain D[(i-1)&1] — both overlap half1(i) exec */
        build_window(Abase + ((uint32_t)((i + 1) & 1)) * 32768u, xw, i + 1, m, selp);
        asm volatile("fence.proxy.async.shared::cta;" ::: "memory");
        if (i > 0)
            drain_d(tmem + (((i - 1) & 1) ? TM_D1 : TM_D0), outb,
                    t0 + 128 * (i - 1) + 32 * (wid & 3) + lane, wg);
        __syncthreads();   /* window i+1 visible; drains done (D[(i+1)&1] free) */

        /* issue half2(i): window i+1 (slot (i+1)&1), ksteps 8..15, accumulate */
        if (wid == 0 && elect_one_pred()) {
            issue_half(sb, d, (uint32_t)(i + 1) & 1u, 1, 0);
            TCGEN05_COMMIT(sb + OFF_MBARB);
        }
    }

    /* tail: wait half2(7) (mbarB phase 7, parity 1), drain D[1] */
    MBARRIER_WAIT_PARITY(sb + OFF_MBARB, 1);
    TCGEN05_FENCE_AFTER();
    drain_d(tmem + TM_D1, outb, t0 + 128 * 7 + 32 * (wid & 3) + lane, wg);

    TCGEN05_FENCE_BEFORE();
    __syncthreads();
    if (wid == 0) TCGEN05_DEALLOC(tmem, 256);

#else  /* ---------------- fp32 fallback (R3 math; non-feature pass) -------- */
    float* xs = (float*)(smem + 1024);          /* 1280 floats */
    float* ff = (float*)(smem + 8192);          /* 80 x 252 floats */

    const float* xb = x + (size_t)b * T_IN;
    for (int i = tid; i < XLEN; i += 256) {
        const int g = t0 + i;
        xs[i] = (g < T_IN) ? xb[g] : 0.0f;
    }
    for (int i = tid; i < N_F * KLEN; i += 256) {
        const int f = i / KLEN;
        const int k = i - f * KLEN;
        ff[f * 252 + k] = g_filt[i];
    }
    __syncthreads();

    const int tx = tid & 63;
    const int ty = tid >> 6;                    /* 0..3 */
    for (int tp = 0; tp < 4; tp++) {
        const float* xp = xs + 256 * tp + tx;
        for (int fb = 0; fb < N_F; fb += 16) {
            const int f4 = fb + ty * 4;
            float acc[4][4];
            #pragma unroll
            for (int a = 0; a < 4; a++)
                #pragma unroll
                for (int j = 0; j < 4; j++) acc[a][j] = 0.0f;
            #pragma unroll 4
            for (int k = 0; k < KLEN; k++) {
                const float x0 = xp[k], x1 = xp[k + 64], x2 = xp[k + 128], x3 = xp[k + 192];
                const float h0 = ff[(f4 + 0) * 252 + k];
                const float h1 = ff[(f4 + 1) * 252 + k];
                const float h2 = ff[(f4 + 2) * 252 + k];
                const float h3 = ff[(f4 + 3) * 252 + k];
                acc[0][0] += x0 * h0; acc[0][1] += x0 * h1; acc[0][2] += x0 * h2; acc[0][3] += x0 * h3;
                acc[1][0] += x1 * h0; acc[1][1] += x1 * h1; acc[1][2] += x1 * h2; acc[1][3] += x1 * h3;
                acc[2][0] += x2 * h0; acc[2][1] += x2 * h1; acc[2][2] += x2 * h2; acc[2][3] += x2 * h3;
                acc[3][0] += x3 * h0; acc[3][1] += x3 * h1; acc[3][2] += x3 * h2; acc[3][3] += x3 * h3;
            }
            #pragma unroll
            for (int j = 0; j < 4; j++) {
                float* op = out + ((size_t)b * N_F + f4 + j) * T_OUT;
                #pragma unroll
                for (int a = 0; a < 4; a++) {
                    const int t = t0 + 256 * tp + tx + 64 * a;
                    if (t < T_OUT) op[t] = acc[a][j];
                }
            }
        }
    }
#endif
}

extern "C" void kernel_launch(void* const* d_in, const int* in_sizes, int n_in,
                              void* d_out, int out_size)
{
    const float* x    = (const float*)d_in[0];
    const float* b1   = (const float*)d_in[1];
    const float* band = (const float*)d_in[2];
    float* out = (float*)d_out;

    cudaFuncSetAttribute(sinc_mma_k, cudaFuncAttributeMaxDynamicSharedMemorySize,
                         SMEM_TOTAL);

    build_filters_k<<<N_F, 256>>>(b1, band);
    sinc_mma_k<<<dim3(NT, N_B), 256, SMEM_TOTAL>>>(x, out);
}

// round 16
// speedup vs baseline: 1.9263x; 1.9263x over previous
#include <cuda_runtime.h>
#include <cuda_fp16.h>
#include <math.h>
#include <float.h>
#include <stdint.h>

#define N_B   32
#define N_F   80
#define KLEN  251
#define T_IN  32000
#define T_OUT (T_IN - KLEN + 1)   /* 31750 */
#define T_TILE 1024               /* per CTA: 8 subtiles of 128 t */
#define NT     32                 /* tiles per batch row */
#define XLEN   1280               /* staged x elems: covers window 8 */

/* ---- arch feature gate: tcgen05 only exists in the sm_10xa pass ---- */
#if defined(__CUDA_ARCH__) && (defined(__CUDA_ARCH_FEAT_SM103_ALL) || \
    defined(__CUDA_ARCH_FEAT_SM100_ALL) || defined(__CUDA_ARCH_FEAT_SM101_ALL))
#define HAS_TC 1
#else
#define HAS_TC 0
#endif

/* ---- dynamic smem layout (bytes) — 110592 total -> 2 CTAs/SM ---- */
#define OFF_TMEM  0
#define OFF_MBAR  16
#define OFF_XH    1024            /* 1280 fp16 = 2560B, ends 3584 */
#define OFF_A     4096            /* 2 window slots x 32768B, ends 69632 */
#define OFF_FH    69632           /* 80x256 fp16 blocked SW128 = 40960B */
#define SMEM_TOTAL 110592

/* TMEM: double-buffered D, 128-col aligned bases; alloc 256 cols/CTA */
#define TM_D0 0
#define TM_D1 128

/* ---- device globals (no allocs allowed) ---- */
__device__ float         g_filt[N_F * KLEN];     /* fp32, fallback only */
__device__ unsigned char g_hb[40960];            /* blocked+swizzled fp16 h */

/* filter (f,k) -> byte offset, blocked SW128: atom = 8f x 64k (1024B),
   10 f-atoms, 4 k-atoms, atom_off = (f>>3) + (k>>6)*10 */
__host__ __device__ __forceinline__ uint32_t filt_boff(int f, int k) {
    uint32_t o = ((uint32_t)(f >> 3) + (uint32_t)(k >> 6) * 10u) * 1024u
               + (uint32_t)(f & 7) * 128u + (uint32_t)(k & 63) * 2u;
    return o ^ ((o >> 3) & 0x70);
}

/* ---------------- kernel 1: build filters (validated math) ----------------- */
__global__ void build_filters_k(const float* __restrict__ b1,
                                const float* __restrict__ band)
{
    const int f = blockIdx.x;
    const int i = threadIdx.x;
    __shared__ float red[256];

    const float min_f = 50.0f / 16000.0f;
    const float beg   = fabsf(b1[f])   + min_f;
    const float endf  = beg + fabsf(band[f]) + min_f;
    const float twopi = 6.283185307179586f;

    float bp = 0.0f;
    float v  = -FLT_MAX;
    if (i < KLEN) {
        const int d = i - 125;
        float sb, se;
        if (d == 0) { sb = 1.0f; se = 1.0f; }
        else {
            const float tr = fabsf((float)d) * (1.0f / 16000.0f);
            const float ab = twopi * (beg  * 16000.0f) * tr;
            const float ae = twopi * (endf * 16000.0f) * tr;
            sb = sinf(ab) / ab;
            se = sinf(ae) / ae;
        }
        bp = 2.0f * endf * se - 2.0f * beg * sb;
        v  = bp;
    }
    red[i] = v;
    __syncthreads();
    #pragma unroll
    for (int s = 128; s > 0; s >>= 1) {
        if (i < s) red[i] = fmaxf(red[i], red[i + s]);
        __syncthreads();
    }
    const float mx = red[0];

    float val = 0.0f;
    if (i < KLEN) {
        const float n = (251.0f * (float)i) / 250.0f;
        const float w = 0.54f - 0.46f * cosf(twopi * n / 251.0f);
        val = (bp / mx) * w;
        g_filt[f * KLEN + i] = val;
    }
    if (i < 256) {  /* all 256 padded taps (val=0 beyond KLEN) */
        *(__half*)(g_hb + filt_boff(f, i)) = __float2half(val);
    }
}

#if HAS_TC
/* ---------------- PTX helpers (sm_103a pass only) -------------------------- */
__device__ __forceinline__ uint32_t elect_one_pred() {
    uint32_t p;
    asm volatile("{\n\t.reg .pred p;\n\telect.sync _|p, 0xFFFFFFFF;\n\t"
                 "selp.b32 %0, 1, 0, p;\n\t}" : "=r"(p));
    return p;
}
__device__ __forceinline__ uint32_t smem_to_u32(const void* p) {
    uint32_t a;
    asm("{ .reg .u64 t; cvta.to.shared.u64 t, %1; cvt.u32.u64 %0, t; }" : "=r"(a) : "l"(p));
    return a;
}
#define MBARRIER_INIT(addr, cnt) \
    asm volatile("mbarrier.init.shared.b64 [%0], %1;" :: "r"((uint32_t)(addr)), "r"((uint32_t)(cnt)) : "memory")
#define MBARRIER_WAIT_PARITY(mbar_a, par) do { \
    uint32_t _m = (uint32_t)(mbar_a), _p = (uint32_t)(par), _d; \
    asm volatile("{\n\t.reg .pred p;\n\t" \
        "mbarrier.try_wait.parity.acquire.cta.shared::cta.b64 p, [%1], %2;\n\t" \
        "selp.b32 %0, 1, 0, p;\n\t}" : "=r"(_d) : "r"(_m), "r"(_p) : "memory"); \
    if (!_d) { \
        asm volatile("{\n\t.reg .pred P1;\n\t" \
            "WL_%=:\n\t" \
            "mbarrier.try_wait.parity.acquire.cta.shared::cta.b64 P1, [%0], %1, 0x989680;\n\t" \
            "@P1 bra.uni WD_%=;\n\t" \
            "bra.uni WL_%=;\n\t" \
            "WD_%=:\n\t}" :: "r"(_m), "r"(_p) : "memory"); \
    } \
} while (0)
#define TCGEN05_ALLOC(res, n) \
    asm volatile("tcgen05.alloc.cta_group::1.sync.aligned.shared::cta.b32 [%0], %1;" \
        :: "r"((uint32_t)(res)), "r"((uint32_t)(n)) : "memory")
#define TCGEN05_DEALLOC(t, n) \
    asm volatile("tcgen05.dealloc.cta_group::1.sync.aligned.b32 %0, %1;" :: "r"(t), "r"((uint32_t)(n)))
#define TCGEN05_WAIT_LD() asm volatile("tcgen05.wait::ld.sync.aligned;" ::: "memory")
#define TCGEN05_FENCE_BEFORE() asm volatile("tcgen05.fence::before_thread_sync;" ::: "memory")
#define TCGEN05_FENCE_AFTER()  asm volatile("tcgen05.fence::after_thread_sync;" ::: "memory")
#define TCGEN05_COMMIT(mbar) \
    asm volatile("tcgen05.commit.cta_group::1.mbarrier::arrive::one.shared::cluster.b64 [%0];" \
        :: "r"((uint32_t)(mbar)) : "memory")

/* SS-mode f16 MMA (validated form, cg1) */
__device__ __forceinline__ void mma_f16_ss(uint32_t d, uint64_t ad, uint64_t bd,
                                           uint32_t idesc, uint32_t en) {
    uint32_t z = 0;
    asm volatile("{\n\t.reg .pred p;\n\tsetp.ne.u32 p, %5, 0;\n\t"
        "tcgen05.mma.cta_group::1.kind::f16 [%0], %1, %2, %3, {%4, %4, %4, %4}, p;\n\t}"
        :: "r"(d), "l"(ad), "l"(bd), "r"(idesc), "r"(z), "r"(en) : "memory");
}
#define TCGEN05_LD_32X32B_X32(r, tmem_addr) \
    asm volatile("tcgen05.ld.sync.aligned.32x32b.x32.b32 " \
        "{%0, %1, %2, %3, %4, %5, %6, %7, %8, %9, %10, %11, %12, %13, %14, %15, " \
        " %16, %17, %18, %19, %20, %21, %22, %23, %24, %25, %26, %27, %28, %29, %30, %31}, [%32];" \
        : "=r"((r)[0]),  "=r"((r)[1]),  "=r"((r)[2]),  "=r"((r)[3]), \
          "=r"((r)[4]),  "=r"((r)[5]),  "=r"((r)[6]),  "=r"((r)[7]), \
          "=r"((r)[8]),  "=r"((r)[9]),  "=r"((r)[10]), "=r"((r)[11]), \
          "=r"((r)[12]), "=r"((r)[13]), "=r"((r)[14]), "=r"((r)[15]), \
          "=r"((r)[16]), "=r"((r)[17]), "=r"((r)[18]), "=r"((r)[19]), \
          "=r"((r)[20]), "=r"((r)[21]), "=r"((r)[22]), "=r"((r)[23]), \
          "=r"((r)[24]), "=r"((r)[25]), "=r"((r)[26]), "=r"((r)[27]), \
          "=r"((r)[28]), "=r"((r)[29]), "=r"((r)[30]), "=r"((r)[31]) \
        : "r"(tmem_addr))
#define TCGEN05_LD_32X32B_X16(r, tmem_addr) \
    asm volatile("tcgen05.ld.sync.aligned.32x32b.x16.b32 " \
        "{%0, %1, %2, %3, %4, %5, %6, %7, %8, %9, %10, %11, %12, %13, %14, %15}, [%16];" \
        : "=r"((r)[0]),  "=r"((r)[1]),  "=r"((r)[2]),  "=r"((r)[3]), \
          "=r"((r)[4]),  "=r"((r)[5]),  "=r"((r)[6]),  "=r"((r)[7]), \
          "=r"((r)[8]),  "=r"((r)[9]),  "=r"((r)[10]), "=r"((r)[11]), \
          "=r"((r)[12]), "=r"((r)[13]), "=r"((r)[14]), "=r"((r)[15]) \
        : "r"(tmem_addr))

/* SW128 K-major descriptor base (validated constants) */
static constexpr uint64_t SMEM_DESC_BASE_SW128 =
    (uint64_t(2)  << 61) | (uint64_t(1) << 46) | (uint64_t(64) << 32) | (uint64_t(1) << 16);
#define MAKE_SMEM_DESC(base_addr) \
    (SMEM_DESC_BASE_SW128 | ((uint64_t)((base_addr) >> 4) & 0x3FFF))

/* idesc kind::f16: F32 accum, F16 a/b (atype=btype=0), M=128, N=64 / N=16 */
static constexpr uint32_t IDESC_N64 = (1u << 4) | (8u << 17) | (8u << 24);
static constexpr uint32_t IDESC_N16 = (1u << 4) | (2u << 17) | (8u << 24);

/* ---- build chunks [c0, c0+8) of one 128x128 window into a slot.
   Window w: row m holds x[t0 + 128*w + m + k'], k' = 0..127.
   Blocked SW128: atom = 8m x 64k; 16 m-atoms, 2 k-atoms (stride 16 atoms). ---- */
__device__ __forceinline__ void build_window(char* Abuf, const uint32_t* xw,
                                             int w, int m, int c0, uint32_t selp)
{
    const uint32_t w0i = (uint32_t)(128 * w + m) >> 1;
    uint32_t prev = xw[w0i + 4 * c0];
    #pragma unroll 1
    for (int cj = c0; cj < c0 + 8; cj++) {  /* 16B chunk = 8 fp16 */
        uint32_t q0, q1, q2, q3, nx;
        nx = xw[w0i + 4*cj + 1]; q0 = __byte_perm(prev, nx, selp); prev = nx;
        nx = xw[w0i + 4*cj + 2]; q1 = __byte_perm(prev, nx, selp); prev = nx;
        nx = xw[w0i + 4*cj + 3]; q2 = __byte_perm(prev, nx, selp); prev = nx;
        nx = xw[w0i + 4*cj + 4]; q3 = __byte_perm(prev, nx, selp); prev = nx;
        uint32_t o = ((uint32_t)(m >> 3) + (uint32_t)(cj >> 3) * 16u) * 1024u
                   + (uint32_t)(m & 7) * 128u + (uint32_t)(cj & 7) * 16u;
        o ^= (o >> 3) & 0x70;
        *(uint4*)(Abuf + o) = make_uint4(q0, q1, q2, q3);
    }
}

/* ---- drain one D buffer, split across warpgroups.
   LDTM warp-collective: always executed; per-lane stores guarded. ---- */
__device__ __forceinline__ void drain_d(uint32_t db, float* __restrict__ outb,
                                        int t, int wg)
{
    if (wg == 0) {     /* cols 0..31 and 64..79 */
        uint32_t r0[32], r2[16];
        TCGEN05_LD_32X32B_X32(r0, db);
        TCGEN05_LD_32X32B_X16(r2, db + 64);
        TCGEN05_WAIT_LD();
        if (t < T_OUT) {
            float* op = outb + t;
            #pragma unroll
            for (int c = 0; c < 32; c++) op[(size_t)c * T_OUT] = __uint_as_float(r0[c]);
            #pragma unroll
            for (int c = 0; c < 16; c++) op[(size_t)(64 + c) * T_OUT] = __uint_as_float(r2[c]);
        }
    } else {           /* cols 32..63 */
        uint32_t r1[32];
        TCGEN05_LD_32X32B_X32(r1, db + 32);
        TCGEN05_WAIT_LD();
        if (t < T_OUT) {
            float* op = outb + t;
            #pragma unroll
            for (int c = 0; c < 32; c++) op[(size_t)(32 + c) * T_OUT] = __uint_as_float(r1[c]);
        }
    }
}
#endif /* HAS_TC */

/* ---------------- main kernel: tensor path OR fp32 fallback --------------- */
__global__ void __launch_bounds__(256, 2)
#if HAS_TC
__cluster_dims__(1, 1, 1)
#endif
sinc_mma_k(const float* __restrict__ x, float* __restrict__ out)
{
    extern __shared__ char smem[];
    const int tid = threadIdx.x;
    const int b   = blockIdx.y;
    const int t0  = blockIdx.x * T_TILE;

#if HAS_TC
    const uint32_t sb = smem_to_u32(smem);
    const int wid  = tid >> 5;
    const int lane = tid & 31;
    const int wg   = tid >> 7;          /* warpgroup 0/1 */
    const int m    = tid & 127;         /* A row 0..127 */
    const int c0   = wg * 8;            /* chunk half this wg builds */

    if (wid == 0) TCGEN05_ALLOC(sb + OFF_TMEM, 256);
    if (tid == 0) MBARRIER_INIT(sb + OFF_MBAR, 1);

    /* stage x as fp16 */
    {
        const float* xb = x + (size_t)b * T_IN;
        __half* xh = (__half*)(smem + OFF_XH);
        for (int i = tid; i < XLEN; i += 256) {
            const int g = t0 + i;
            xh[i] = __float2half((g < T_IN) ? xb[g] : 0.0f);
        }
    }
    /* stage filters (raw copy preserves blocked+swizzled layout) */
    {
        const uint4* sh = (const uint4*)g_hb;
        uint4* dh = (uint4*)(smem + OFF_FH);
        for (int j = tid; j < 2560; j += 256) dh[j] = sh[j];
    }
    __syncthreads();

    uint32_t tmem;
    asm volatile("ld.shared.b32 %0, [%1];" : "=r"(tmem) : "r"(sb + OFF_TMEM));

    const uint32_t selp = (m & 1) ? 0x5432u : 0x3210u;
    const uint32_t* xw = (const uint32_t*)(smem + OFF_XH);
    char* Abase = smem + OFF_A;
    float* outb = out + (size_t)b * N_F * T_OUT;

    /* prologue: windows 0 (slot 0) and 1 (slot 1), both wgs build half each */
    build_window(Abase,         xw, 0, m, c0, selp);
    build_window(Abase + 32768, xw, 1, m, c0, selp);
    asm volatile("fence.proxy.async.shared::cta;" ::: "memory");

    #pragma unroll 1
    for (int i = 0; i < 8; i++) {
        /* wait commit(i-1): frees slot (i+1)&1 (window i-1) AND D[(i-1)&1] */
        if (i > 0) {
            MBARRIER_WAIT_PARITY(sb + OFF_MBAR, (i - 1) & 1);
            TCGEN05_FENCE_AFTER();
            build_window(Abase + ((uint32_t)((i + 1) & 1)) * 32768u,
                         xw, i + 1, m, c0, selp);
            asm volatile("fence.proxy.async.shared::cta;" ::: "memory");
        }
        __syncthreads();

        /* ---- issue MMA(i): single fp16 pass, 16 ksteps (8 per window),
           windows i (slot i&1) and i+1 (slot (i+1)&1); single commit ---- */
        if (wid == 0 && elect_one_pred()) {
            const uint32_t d = tmem + ((i & 1) ? TM_D1 : TM_D0);
            const uint64_t bd0 = MAKE_SMEM_DESC(sb + OFF_FH);          /* f0..63  */
            const uint64_t bd1 = MAKE_SMEM_DESC(sb + OFF_FH + 8192);   /* f64..79 */
            #pragma unroll 1
            for (int h = 0; h < 2; h++) {
                const uint32_t slot = (uint32_t)(i + h) & 1u;
                const uint64_t ad0 = MAKE_SMEM_DESC(sb + OFF_A + slot * 32768u);
                #pragma unroll
                for (int ks = 0; ks < 8; ks++) {
                    const uint64_t ao = 1024u * (ks >> 2) + 2u * (ks & 3);
                    const int gk = 8 * h + ks;
                    const uint64_t bo = 640u * (gk >> 2) + 2u * (gk & 3);
                    const uint32_t en = (h == 0 && ks == 0) ? 0u : 1u;
                    mma_f16_ss(d,      ad0 + ao, bd0 + bo, IDESC_N64, en);
                    mma_f16_ss(d + 64, ad0 + ao, bd1 + bo, IDESC_N16, en);
                }
            }
            TCGEN05_COMMIT(sb + OFF_MBAR);
        }

        /* ---- drain D[(i-1)&1] (complete per wait above); overlaps MMA(i) */
        if (i > 0)
            drain_d(tmem + (((i - 1) & 1) ? TM_D1 : TM_D0), outb,
                    t0 + 128 * (i - 1) + 32 * (wid & 3) + lane, wg);
    }

    /* tail: wait commit(7) (parity 1), drain D[1] */
    MBARRIER_WAIT_PARITY(sb + OFF_MBAR, 1);
    TCGEN05_FENCE_AFTER();
    drain_d(tmem + TM_D1, outb, t0 + 128 * 7 + 32 * (wid & 3) + lane, wg);

    TCGEN05_FENCE_BEFORE();
    __syncthreads();
    if (wid == 0) TCGEN05_DEALLOC(tmem, 256);

#else  /* ---------------- fp32 fallback (R3 math; non-feature pass) -------- */
    float* xs = (float*)(smem + 1024);          /* 1280 floats */
    float* ff = (float*)(smem + 8192);          /* 80 x 252 floats */

    const float* xb = x + (size_t)b * T_IN;
    for (int i = tid; i < XLEN; i += 256) {
        const int g = t0 + i;
        xs[i] = (g < T_IN) ? xb[g] : 0.0f;
    }
    for (int i = tid; i < N_F * KLEN; i += 256) {
        const int f = i / KLEN;
        const int k = i - f * KLEN;
        ff[f * 252 + k] = g_filt[i];
    }
    __syncthreads();

    const int tx = tid & 63;
    const int ty = tid >> 6;                    /* 0..3 */
    for (int tp = 0; tp < 4; tp++) {
        const float* xp = xs + 256 * tp + tx;
        for (int fb = 0; fb < N_F; fb += 16) {
            const int f4 = fb + ty * 4;
            float acc[4][4];
            #pragma unroll
            for (int a = 0; a < 4; a++)
                #pragma unroll
                for (int j = 0; j < 4; j++) acc[a][j] = 0.0f;
            #pragma unroll 4
            for (int k = 0; k < KLEN; k++) {
                const float x0 = xp[k], x1 = xp[k + 64], x2 = xp[k + 128], x3 = xp[k + 192];
                const float h0 = ff[(f4 + 0) * 252 + k];
                const float h1 = ff[(f4 + 1) * 252 + k];
                const float h2 = ff[(f4 + 2) * 252 + k];
                const float h3 = ff[(f4 + 3) * 252 + k];
                acc[0][0] += x0 * h0; acc[0][1] += x0 * h1; acc[0][2] += x0 * h2; acc[0][3] += x0 * h3;
                acc[1][0] += x1 * h0; acc[1][1] += x1 * h1; acc[1][2] += x1 * h2; acc[1][3] += x1 * h3;
                acc[2][0] += x2 * h0; acc[2][1] += x2 * h1; acc[2][2] += x2 * h2; acc[2][3] += x2 * h3;
                acc[3][0] += x3 * h0; acc[3][1] += x3 * h1; acc[3][2] += x3 * h2; acc[3][3] += x3 * h3;
            }
            #pragma unroll
            for (int j = 0; j < 4; j++) {
                float* op = out + ((size_t)b * N_F + f4 + j) * T_OUT;
                #pragma unroll
                for (int a = 0; a < 4; a++) {
                    const int t = t0 + 256 * tp + tx + 64 * a;
                    if (t < T_OUT) op[t] = acc[a][j];
                }
            }
        }
    }
#endif
}

extern "C" void kernel_launch(void* const* d_in, const int* in_sizes, int n_in,
                              void* d_out, int out_size)
{
    const float* x    = (const float*)d_in[0];
    const float* b1   = (const float*)d_in[1];
    const float* band = (const float*)d_in[2];
    float* out = (float*)d_out;

    cudaFuncSetAttribute(sinc_mma_k, cudaFuncAttributeMaxDynamicSharedMemorySize,
                         SMEM_TOTAL);

    build_filters_k<<<N_F, 256>>>(b1, band);
    sinc_mma_k<<<dim3(NT, N_B), 256, SMEM_TOTAL>>>(x, out);
}